// round 1
// baseline (speedup 1.0000x reference)
#include <cuda_runtime.h>
#include <math.h>

#define C_CH   128
#define SPA    4096
#define BATCH  2
#define HEADS  4
#define DHEAD  32
#define GROUPS 32
#define CPG    4        // channels per group = C_CH/GROUPS
#define HTOT   128      // HEADS*DHEAD
#define QKV_R  384      // 3*HTOT
#define EPSV   1e-5f

// Scratch (device globals: allocation-free per harness rules)
__device__ float g_qkv[BATCH * QKV_R * SPA];   // [b][o][s], o: 0..127 q, 128..255 k, 256..383 v
__device__ float g_ao [BATCH * HTOT * SPA];    // attention output [b][n*32+d][s]
__device__ float g_mean[BATCH * GROUPS];
__device__ float g_rstd[BATCH * GROUPS];

// ---------------------------------------------------------------------------
// 1) GroupNorm statistics: one block per (b, group). Each group's data is a
//    contiguous slab of CPG*SPA = 16384 floats.
// ---------------------------------------------------------------------------
__global__ __launch_bounds__(256) void gn_stats(const float* __restrict__ x) {
    int bg = blockIdx.x;                       // b*GROUPS + g
    const float* p = x + (size_t)bg * (CPG * SPA);
    float s1 = 0.f, s2 = 0.f;
    for (int i = threadIdx.x; i < CPG * SPA; i += 256) {
        float v = p[i];
        s1 += v;
        s2 += v * v;
    }
    __shared__ float r1[8], r2[8];
    #pragma unroll
    for (int o = 16; o; o >>= 1) {
        s1 += __shfl_down_sync(0xffffffffu, s1, o);
        s2 += __shfl_down_sync(0xffffffffu, s2, o);
    }
    int w = threadIdx.x >> 5, l = threadIdx.x & 31;
    if (l == 0) { r1[w] = s1; r2[w] = s2; }
    __syncthreads();
    if (w == 0) {
        s1 = (l < 8) ? r1[l] : 0.f;
        s2 = (l < 8) ? r2[l] : 0.f;
        #pragma unroll
        for (int o = 4; o; o >>= 1) {
            s1 += __shfl_down_sync(0xffffffffu, s1, o);
            s2 += __shfl_down_sync(0xffffffffu, s2, o);
        }
        if (l == 0) {
            const float invN = 1.0f / (CPG * SPA);
            float mean = s1 * invN;
            float var  = s2 * invN - mean * mean;
            g_mean[bg] = mean;
            g_rstd[bg] = rsqrtf(var + EPSV);
        }
    }
}

// ---------------------------------------------------------------------------
// 2) QKV GEMM with fused GroupNorm on the activation load.
//    Out[b][o][s] = sum_c W[o][c] * xn[b][c][s]
//    Tiles: BM=64 (o) x BN=64 (s) x BK=32, 256 threads, 4x4 per thread.
// ---------------------------------------------------------------------------
#define BM 64
#define BN 64
#define BK 32

__global__ __launch_bounds__(256) void qkv_gemm(const float* __restrict__ x,
                                                const float* __restrict__ w,
                                                const float* __restrict__ gamma,
                                                const float* __restrict__ beta) {
    int b  = blockIdx.z;
    int m0 = blockIdx.y * BM;
    int n0 = blockIdx.x * BN;
    __shared__ float As[BM * BK];
    __shared__ float Bs[BK * BN];
    int tid = threadIdx.x;
    int tx = tid & 15, ty = tid >> 4;
    float acc[4][4] = {};
    const float* xb = x + (size_t)b * C_CH * SPA;

    for (int k0 = 0; k0 < C_CH; k0 += BK) {
        for (int i = tid; i < BM * BK; i += 256) {
            int row = i / BK, col = i % BK;
            As[i] = w[(size_t)(m0 + row) * C_CH + k0 + col];
        }
        for (int i = tid; i < BK * BN; i += 256) {
            int kk = i / BN, j = i % BN;
            int c = k0 + kk;
            int g = c >> 2;                     // c / CPG
            float mv = g_mean[b * GROUPS + g];
            float rs = g_rstd[b * GROUPS + g];
            float v = xb[(size_t)c * SPA + n0 + j];
            Bs[i] = (v - mv) * rs * gamma[c] + beta[c];
        }
        __syncthreads();
        #pragma unroll
        for (int kk = 0; kk < BK; kk++) {
            float a[4], bb[4];
            #pragma unroll
            for (int i = 0; i < 4; i++) a[i] = As[(ty * 4 + i) * BK + kk];
            #pragma unroll
            for (int j = 0; j < 4; j++) bb[j] = Bs[kk * BN + tx * 4 + j];
            #pragma unroll
            for (int i = 0; i < 4; i++)
                #pragma unroll
                for (int j = 0; j < 4; j++) acc[i][j] += a[i] * bb[j];
        }
        __syncthreads();
    }
    float* outb = g_qkv + (size_t)b * QKV_R * SPA;
    #pragma unroll
    for (int i = 0; i < 4; i++)
        #pragma unroll
        for (int j = 0; j < 4; j++)
            outb[(size_t)(m0 + ty * 4 + i) * SPA + n0 + tx * 4 + j] = acc[i][j];
}

// ---------------------------------------------------------------------------
// 3) Flash attention: thread-per-query. Block = 128 threads = 128 queries.
//    Grid: (q_tiles=32, heads=4, batch=2).
//    K/V tiles of 64 keys staged in smem rows of 36 floats (9 float4):
//      - cooperative fill does STS.128, group index (9j+d4)%8 -> conflict-free
//      - inner-loop reads are whole-warp broadcasts of float4 (no conflicts)
// ---------------------------------------------------------------------------
#define TQ 128
#define TJ 64
#define KROW 36   // padded row: 9 float4

__global__ __launch_bounds__(128) void attn_kernel() {
    int qt = blockIdx.x;
    int n  = blockIdx.y;
    int b  = blockIdx.z;
    int t  = threadIdx.x;

    __shared__ float sk[TJ * KROW];
    __shared__ float sv[TJ * KROW];
    __shared__ float sq[TQ * 33];

    const float* qkv_b = g_qkv + (size_t)b * QKV_R * SPA;
    const float* qptr = qkv_b + (size_t)(n * DHEAD) * SPA;
    const float* kptr = qkv_b + (size_t)(HTOT + n * DHEAD) * SPA;
    const float* vptr = qkv_b + (size_t)(2 * HTOT + n * DHEAD) * SPA;
    int s0 = qt * TQ;

    // stage Q (coalesced gmem, conflict-free smem), fold softmax scale into q
    for (int i = t; i < TQ * DHEAD; i += 128) {
        int d = i / TQ, sl = i % TQ;
        sq[sl * 33 + d] = qptr[(size_t)d * SPA + s0 + sl];
    }
    __syncthreads();
    const float scale = 0.17677669529663687f;   // 1/sqrt(32)
    float q[DHEAD];
    #pragma unroll
    for (int d = 0; d < DHEAD; d++) q[d] = sq[t * 33 + d] * scale;

    float m = -1e30f, l = 0.f;
    float acc[DHEAD];
    #pragma unroll
    for (int d = 0; d < DHEAD; d++) acc[d] = 0.f;

    for (int j0 = 0; j0 < SPA; j0 += TJ) {
        __syncthreads();
        // fill K/V tile: i -> (j = i%TJ, d4 = i/TJ); 4 strided LDG.32 (each
        // coalesced across lanes) then one conflict-free STS.128 per element
        for (int i = t; i < TJ * 8; i += 128) {
            int j = i & (TJ - 1), d4 = i >> 6;
            const float* kp = kptr + (size_t)(d4 * 4) * SPA + j0 + j;
            float4 kk;
            kk.x = kp[0]; kk.y = kp[SPA]; kk.z = kp[2 * SPA]; kk.w = kp[3 * SPA];
            *(float4*)&sk[j * KROW + d4 * 4] = kk;
            const float* vp = vptr + (size_t)(d4 * 4) * SPA + j0 + j;
            float4 vv;
            vv.x = vp[0]; vv.y = vp[SPA]; vv.z = vp[2 * SPA]; vv.w = vp[3 * SPA];
            *(float4*)&sv[j * KROW + d4 * 4] = vv;
        }
        __syncthreads();

        for (int j = 0; j < TJ; j++) {
            const float4* kr = (const float4*)&sk[j * KROW];
            // 4-way split accumulators for ILP
            float p0 = 0.f, p1 = 0.f, p2 = 0.f, p3 = 0.f;
            #pragma unroll
            for (int g = 0; g < 8; g += 4) {
                float4 k0 = kr[g + 0], k1 = kr[g + 1], k2 = kr[g + 2], k3 = kr[g + 3];
                p0 += q[4*g+ 0]*k0.x + q[4*g+ 1]*k0.y + q[4*g+ 2]*k0.z + q[4*g+ 3]*k0.w;
                p1 += q[4*g+ 4]*k1.x + q[4*g+ 5]*k1.y + q[4*g+ 6]*k1.z + q[4*g+ 7]*k1.w;
                p2 += q[4*g+ 8]*k2.x + q[4*g+ 9]*k2.y + q[4*g+10]*k2.z + q[4*g+11]*k2.w;
                p3 += q[4*g+12]*k3.x + q[4*g+13]*k3.y + q[4*g+14]*k3.z + q[4*g+15]*k3.w;
            }
            float sc = (p0 + p1) + (p2 + p3);

            if (sc > m) {                       // rare after warmup
                float corr = __expf(m - sc);
                l *= corr;
                #pragma unroll
                for (int d = 0; d < DHEAD; d++) acc[d] *= corr;
                m = sc;
            }
            float p = __expf(sc - m);
            l += p;
            const float4* vr = (const float4*)&sv[j * KROW];
            #pragma unroll
            for (int g = 0; g < 8; g++) {
                float4 vv = vr[g];
                acc[4*g+0] += p * vv.x;
                acc[4*g+1] += p * vv.y;
                acc[4*g+2] += p * vv.z;
                acc[4*g+3] += p * vv.w;
            }
        }
    }

    __syncthreads();
    float inv = 1.0f / l;
    #pragma unroll
    for (int d = 0; d < DHEAD; d++) sq[t * 33 + d] = acc[d] * inv;
    __syncthreads();
    float* aob = g_ao + (size_t)b * HTOT * SPA + (size_t)(n * DHEAD) * SPA;
    for (int i = t; i < TQ * DHEAD; i += 128) {
        int d = i / TQ, sl = i % TQ;
        aob[(size_t)d * SPA + s0 + sl] = sq[sl * 33 + d];
    }
}

// ---------------------------------------------------------------------------
// 4) Output projection: y[b][c][s] = sum_h Wout[c][h]*ao[b][h][s] + bias[c]
// ---------------------------------------------------------------------------
__global__ __launch_bounds__(256) void out_gemm(const float* __restrict__ w,
                                                const float* __restrict__ bias,
                                                float* __restrict__ y) {
    int b  = blockIdx.z;
    int m0 = blockIdx.y * BM;
    int n0 = blockIdx.x * BN;
    __shared__ float As[BM * BK];
    __shared__ float Bs[BK * BN];
    int tid = threadIdx.x;
    int tx = tid & 15, ty = tid >> 4;
    float acc[4][4] = {};
    const float* ab = g_ao + (size_t)b * HTOT * SPA;

    for (int k0 = 0; k0 < HTOT; k0 += BK) {
        for (int i = tid; i < BM * BK; i += 256) {
            int row = i / BK, col = i % BK;
            As[i] = w[(size_t)(m0 + row) * HTOT + k0 + col];
        }
        for (int i = tid; i < BK * BN; i += 256) {
            int kk = i / BN, j = i % BN;
            Bs[i] = ab[(size_t)(k0 + kk) * SPA + n0 + j];
        }
        __syncthreads();
        #pragma unroll
        for (int kk = 0; kk < BK; kk++) {
            float a[4], bb[4];
            #pragma unroll
            for (int i = 0; i < 4; i++) a[i] = As[(ty * 4 + i) * BK + kk];
            #pragma unroll
            for (int j = 0; j < 4; j++) bb[j] = Bs[kk * BN + tx * 4 + j];
            #pragma unroll
            for (int i = 0; i < 4; i++)
                #pragma unroll
                for (int j = 0; j < 4; j++) acc[i][j] += a[i] * bb[j];
        }
        __syncthreads();
    }
    #pragma unroll
    for (int i = 0; i < 4; i++) {
        float bv = bias[m0 + ty * 4 + i];
        #pragma unroll
        for (int j = 0; j < 4; j++)
            y[(size_t)(b * C_CH + m0 + ty * 4 + i) * SPA + n0 + tx * 4 + j] =
                acc[i][j] + bv;
    }
}

// ---------------------------------------------------------------------------
extern "C" void kernel_launch(void* const* d_in, const int* in_sizes, int n_in,
                              void* d_out, int out_size) {
    const float* x     = (const float*)d_in[0];
    const float* gamma = (const float*)d_in[1];
    const float* beta  = (const float*)d_in[2];
    const float* w_qkv = (const float*)d_in[3];
    const float* w_out = (const float*)d_in[4];
    const float* b_out = (const float*)d_in[5];
    float* y = (float*)d_out;

    gn_stats<<<BATCH * GROUPS, 256>>>(x);
    qkv_gemm<<<dim3(SPA / BN, QKV_R / BM, BATCH), 256>>>(x, w_qkv, gamma, beta);
    attn_kernel<<<dim3(SPA / TQ, HEADS, BATCH), 128>>>();
    out_gemm<<<dim3(SPA / BN, C_CH / BM, BATCH), 256>>>(w_out, b_out, y);
}

// round 3
// speedup vs baseline: 1.4307x; 1.4307x over previous
#include <cuda_runtime.h>
#include <math.h>

#define C_CH   128
#define SPA    4096
#define BATCH  2
#define HEADS  4
#define DHEAD  32
#define GROUPS 32
#define CPG    4
#define HTOT   128
#define QKV_R  384
#define EPSV   1e-5f

#define NC     4                 // split-K chunks over keys
#define CHUNK  (SPA / NC)        // 1024 keys per chunk

typedef unsigned long long ull;

// Scratch (device globals: allocation-free per harness rules)
__device__ float g_qkv [BATCH * QKV_R * SPA];          // [b][o][s]
__device__ float g_ao  [BATCH * HTOT * SPA];           // attention output
__device__ float g_mean[BATCH * GROUPS];
__device__ float g_rstd[BATCH * GROUPS];
__device__ float g_pacc[BATCH * HEADS * NC * DHEAD * SPA];  // partial acc
__device__ float g_pm  [BATCH * HEADS * NC * SPA];          // partial max
__device__ float g_pl  [BATCH * HEADS * NC * SPA];          // partial sum

// ---- Blackwell packed f32x2 helpers (FFMA2 only reachable via PTX) --------
__device__ __forceinline__ void ffma2(ull& d, ull a, ull b) {
    asm("fma.rn.f32x2 %0, %1, %2, %0;" : "+l"(d) : "l"(a), "l"(b));
}
__device__ __forceinline__ ull fadd2(ull a, ull b) {
    ull r; asm("add.rn.f32x2 %0, %1, %2;" : "=l"(r) : "l"(a), "l"(b)); return r;
}
__device__ __forceinline__ ull fmul2(ull a, ull b) {
    ull r; asm("mul.rn.f32x2 %0, %1, %2;" : "=l"(r) : "l"(a), "l"(b)); return r;
}
__device__ __forceinline__ ull pack2(float x, float y) {
    ull r; asm("mov.b64 %0, {%1, %2};" : "=l"(r) : "f"(x), "f"(y)); return r;
}
__device__ __forceinline__ float2 unpack2(ull v) {
    float lo, hi; asm("mov.b64 {%0, %1}, %2;" : "=f"(lo), "=f"(hi) : "l"(v));
    return make_float2(lo, hi);
}

// ---------------------------------------------------------------------------
// 1) GroupNorm statistics
// ---------------------------------------------------------------------------
__global__ __launch_bounds__(256) void gn_stats(const float* __restrict__ x) {
    int bg = blockIdx.x;
    const float* p = x + (size_t)bg * (CPG * SPA);
    float s1 = 0.f, s2 = 0.f;
    for (int i = threadIdx.x; i < CPG * SPA; i += 256) {
        float v = p[i];
        s1 += v; s2 += v * v;
    }
    __shared__ float r1[8], r2[8];
    #pragma unroll
    for (int o = 16; o; o >>= 1) {
        s1 += __shfl_down_sync(0xffffffffu, s1, o);
        s2 += __shfl_down_sync(0xffffffffu, s2, o);
    }
    int w = threadIdx.x >> 5, l = threadIdx.x & 31;
    if (l == 0) { r1[w] = s1; r2[w] = s2; }
    __syncthreads();
    if (w == 0) {
        s1 = (l < 8) ? r1[l] : 0.f;
        s2 = (l < 8) ? r2[l] : 0.f;
        #pragma unroll
        for (int o = 4; o; o >>= 1) {
            s1 += __shfl_down_sync(0xffffffffu, s1, o);
            s2 += __shfl_down_sync(0xffffffffu, s2, o);
        }
        if (l == 0) {
            const float invN = 1.0f / (CPG * SPA);
            float mean = s1 * invN;
            float var  = s2 * invN - mean * mean;
            g_mean[bg] = mean;
            g_rstd[bg] = rsqrtf(var + EPSV);
        }
    }
}

// ---------------------------------------------------------------------------
// 2) QKV GEMM with fused GroupNorm on the activation load
// ---------------------------------------------------------------------------
#define BM 64
#define BN 64
#define BK 32

__global__ __launch_bounds__(256) void qkv_gemm(const float* __restrict__ x,
                                                const float* __restrict__ w,
                                                const float* __restrict__ gamma,
                                                const float* __restrict__ beta) {
    int b  = blockIdx.z;
    int m0 = blockIdx.y * BM;
    int n0 = blockIdx.x * BN;
    __shared__ float As[BM * BK];
    __shared__ float Bs[BK * BN];
    int tid = threadIdx.x;
    int tx = tid & 15, ty = tid >> 4;
    float acc[4][4] = {};
    const float* xb = x + (size_t)b * C_CH * SPA;

    for (int k0 = 0; k0 < C_CH; k0 += BK) {
        for (int i = tid; i < BM * BK; i += 256) {
            int row = i / BK, col = i % BK;
            As[i] = w[(size_t)(m0 + row) * C_CH + k0 + col];
        }
        for (int i = tid; i < BK * BN; i += 256) {
            int kk = i / BN, j = i % BN;
            int c = k0 + kk;
            int g = c >> 2;
            float mv = g_mean[b * GROUPS + g];
            float rs = g_rstd[b * GROUPS + g];
            float v = xb[(size_t)c * SPA + n0 + j];
            Bs[i] = (v - mv) * rs * gamma[c] + beta[c];
        }
        __syncthreads();
        #pragma unroll
        for (int kk = 0; kk < BK; kk++) {
            float a[4], bb[4];
            #pragma unroll
            for (int i = 0; i < 4; i++) a[i] = As[(ty * 4 + i) * BK + kk];
            #pragma unroll
            for (int j = 0; j < 4; j++) bb[j] = Bs[kk * BN + tx * 4 + j];
            #pragma unroll
            for (int i = 0; i < 4; i++)
                #pragma unroll
                for (int j = 0; j < 4; j++) acc[i][j] += a[i] * bb[j];
        }
        __syncthreads();
    }
    float* outb = g_qkv + (size_t)b * QKV_R * SPA;
    #pragma unroll
    for (int i = 0; i < 4; i++)
        #pragma unroll
        for (int j = 0; j < 4; j++)
            outb[(size_t)(m0 + ty * 4 + i) * SPA + n0 + tx * 4 + j] = acc[i][j];
}

// ---------------------------------------------------------------------------
// 3a) Flash attention partial (split-K): thread-per-query, packed f32x2 math.
//     Grid: (q_tiles=32, heads*NC=16, batch=2) = 1024 blocks of 128 threads.
// ---------------------------------------------------------------------------
#define TQ 128
#define TJ 64
#define KROW 36   // padded row: 9 float4 (144 B, 16B-aligned)

__global__ __launch_bounds__(128) void attn_partial() {
    int qt = blockIdx.x;
    int nc = blockIdx.y;                 // n*NC + chunk
    int b  = blockIdx.z;
    int n  = nc >> 2, c = nc & (NC - 1);
    int t  = threadIdx.x;

    __shared__ __align__(16) float smem_buf[2 * TJ * KROW];
    float* sk = smem_buf;
    float* sv = smem_buf + TJ * KROW;

    const float* qkv_b = g_qkv + (size_t)b * QKV_R * SPA;
    const float* qptr = qkv_b + (size_t)(n * DHEAD) * SPA;
    const float* kptr = qkv_b + (size_t)(HTOT + n * DHEAD) * SPA;
    const float* vptr = qkv_b + (size_t)(2 * HTOT + n * DHEAD) * SPA;
    int s0 = qt * TQ;

    // stage Q through smem (coalesced gmem read, transposed), fold scale, pack
    for (int i = t; i < TQ * DHEAD; i += 128) {
        int d = i / TQ, sl = i % TQ;
        smem_buf[sl * 33 + d] = qptr[(size_t)d * SPA + s0 + sl];
    }
    __syncthreads();
    const float scale = 0.17677669529663687f;   // 1/sqrt(32)
    ull qp[16];
    #pragma unroll
    for (int i = 0; i < 16; i++)
        qp[i] = pack2(smem_buf[t * 33 + 2 * i] * scale,
                      smem_buf[t * 33 + 2 * i + 1] * scale);
    __syncthreads();   // done reading Q region before K/V overwrite

    float m = -1e30f, l = 0.f;
    ull accp[16];
    #pragma unroll
    for (int i = 0; i < 16; i++) accp[i] = 0ull;

    int jbeg = c * CHUNK, jend = jbeg + CHUNK;
    for (int j0 = jbeg; j0 < jend; j0 += TJ) {
        // fill K/V tile: coalesced LDG.32 x4, conflict-free STS.128
        for (int i = t; i < TJ * 8; i += 128) {
            int j = i & (TJ - 1), d4 = i >> 6;
            const float* kp = kptr + (size_t)(d4 * 4) * SPA + j0 + j;
            float4 kk;
            kk.x = kp[0]; kk.y = kp[SPA]; kk.z = kp[2 * SPA]; kk.w = kp[3 * SPA];
            *(float4*)&sk[j * KROW + d4 * 4] = kk;
            const float* vp = vptr + (size_t)(d4 * 4) * SPA + j0 + j;
            float4 vv;
            vv.x = vp[0]; vv.y = vp[SPA]; vv.z = vp[2 * SPA]; vv.w = vp[3 * SPA];
            *(float4*)&sv[j * KROW + d4 * 4] = vv;
        }
        __syncthreads();

        for (int j = 0; j < TJ; j++) {
            const ulonglong2* kr = (const ulonglong2*)&sk[j * KROW];
            ull d0 = 0, d1 = 0, d2 = 0, d3 = 0;
            #pragma unroll
            for (int g = 0; g < 8; g += 4) {
                ulonglong2 k0 = kr[g + 0], k1 = kr[g + 1];
                ulonglong2 k2 = kr[g + 2], k3 = kr[g + 3];
                ffma2(d0, qp[2 * g + 0], k0.x);
                ffma2(d0, qp[2 * g + 1], k0.y);
                ffma2(d1, qp[2 * g + 2], k1.x);
                ffma2(d1, qp[2 * g + 3], k1.y);
                ffma2(d2, qp[2 * g + 4], k2.x);
                ffma2(d2, qp[2 * g + 5], k2.y);
                ffma2(d3, qp[2 * g + 6], k3.x);
                ffma2(d3, qp[2 * g + 7], k3.y);
            }
            d0 = fadd2(d0, d1);
            d2 = fadd2(d2, d3);
            d0 = fadd2(d0, d2);
            float2 dd = unpack2(d0);
            float sc = dd.x + dd.y;

            if (sc > m) {                        // rare after warmup
                float corr = __expf(m - sc);
                ull cc = pack2(corr, corr);
                l *= corr;
                #pragma unroll
                for (int i = 0; i < 16; i++) accp[i] = fmul2(accp[i], cc);
                m = sc;
            }
            float p = __expf(sc - m);
            l += p;
            ull pp = pack2(p, p);
            const ulonglong2* vr = (const ulonglong2*)&sv[j * KROW];
            #pragma unroll
            for (int g = 0; g < 8; g++) {
                ulonglong2 vv = vr[g];
                ffma2(accp[2 * g + 0], pp, vv.x);
                ffma2(accp[2 * g + 1], pp, vv.y);
            }
        }
        __syncthreads();
    }

    // write partials (unnormalized)
    size_t base = (size_t)(b * HEADS + n) * NC + c;
    g_pm[base * SPA + s0 + t] = m;
    g_pl[base * SPA + s0 + t] = l;
    float* pa = g_pacc + base * (DHEAD * SPA);
    #pragma unroll
    for (int i = 0; i < 16; i++) {
        float2 v = unpack2(accp[i]);
        pa[(size_t)(2 * i + 0) * SPA + s0 + t] = v.x;
        pa[(size_t)(2 * i + 1) * SPA + s0 + t] = v.y;
    }
}

// ---------------------------------------------------------------------------
// 3b) Combine split-K partials -> g_ao
// ---------------------------------------------------------------------------
__global__ __launch_bounds__(256) void attn_combine() {
    int t = threadIdx.x;
    int s = blockIdx.x * 256 + t;
    int n = blockIdx.y, b = blockIdx.z;
    size_t base = (size_t)(b * HEADS + n) * NC;

    float pm[NC], pl[NC];
    float m = -1e30f;
    #pragma unroll
    for (int c = 0; c < NC; c++) {
        pm[c] = g_pm[(base + c) * SPA + s];
        m = fmaxf(m, pm[c]);
    }
    float wgt[NC];
    float L = 0.f;
    #pragma unroll
    for (int c = 0; c < NC; c++) {
        pl[c] = g_pl[(base + c) * SPA + s];
        wgt[c] = __expf(pm[c] - m);
        L += pl[c] * wgt[c];
    }
    float invL = 1.0f / L;

    float* ao = g_ao + ((size_t)b * HTOT + n * DHEAD) * SPA;
    #pragma unroll
    for (int d = 0; d < DHEAD; d++) {
        float a = 0.f;
        #pragma unroll
        for (int c = 0; c < NC; c++)
            a += g_pacc[((base + c) * DHEAD + d) * SPA + s] * wgt[c];
        ao[(size_t)d * SPA + s] = a * invL;
    }
}

// ---------------------------------------------------------------------------
// 4) Output projection
// ---------------------------------------------------------------------------
__global__ __launch_bounds__(256) void out_gemm(const float* __restrict__ w,
                                                const float* __restrict__ bias,
                                                float* __restrict__ y) {
    int b  = blockIdx.z;
    int m0 = blockIdx.y * BM;
    int n0 = blockIdx.x * BN;
    __shared__ float As[BM * BK];
    __shared__ float Bs[BK * BN];
    int tid = threadIdx.x;
    int tx = tid & 15, ty = tid >> 4;
    float acc[4][4] = {};
    const float* ab = g_ao + (size_t)b * HTOT * SPA;

    for (int k0 = 0; k0 < HTOT; k0 += BK) {
        for (int i = tid; i < BM * BK; i += 256) {
            int row = i / BK, col = i % BK;
            As[i] = w[(size_t)(m0 + row) * HTOT + k0 + col];
        }
        for (int i = tid; i < BK * BN; i += 256) {
            int kk = i / BN, j = i % BN;
            Bs[i] = ab[(size_t)(k0 + kk) * SPA + n0 + j];
        }
        __syncthreads();
        #pragma unroll
        for (int kk = 0; kk < BK; kk++) {
            float a[4], bb[4];
            #pragma unroll
            for (int i = 0; i < 4; i++) a[i] = As[(ty * 4 + i) * BK + kk];
            #pragma unroll
            for (int j = 0; j < 4; j++) bb[j] = Bs[kk * BN + tx * 4 + j];
            #pragma unroll
            for (int i = 0; i < 4; i++)
                #pragma unroll
                for (int j = 0; j < 4; j++) acc[i][j] += a[i] * bb[j];
        }
        __syncthreads();
    }
    #pragma unroll
    for (int i = 0; i < 4; i++) {
        float bv = bias[m0 + ty * 4 + i];
        #pragma unroll
        for (int j = 0; j < 4; j++)
            y[(size_t)(b * C_CH + m0 + ty * 4 + i) * SPA + n0 + tx * 4 + j] =
                acc[i][j] + bv;
    }
}

// ---------------------------------------------------------------------------
extern "C" void kernel_launch(void* const* d_in, const int* in_sizes, int n_in,
                              void* d_out, int out_size) {
    const float* x     = (const float*)d_in[0];
    const float* gamma = (const float*)d_in[1];
    const float* beta  = (const float*)d_in[2];
    const float* w_qkv = (const float*)d_in[3];
    const float* w_out = (const float*)d_in[4];
    const float* b_out = (const float*)d_in[5];
    float* y = (float*)d_out;

    gn_stats<<<BATCH * GROUPS, 256>>>(x);
    qkv_gemm<<<dim3(SPA / BN, QKV_R / BM, BATCH), 256>>>(x, w_qkv, gamma, beta);
    attn_partial<<<dim3(SPA / TQ, HEADS * NC, BATCH), 128>>>();
    attn_combine<<<dim3(SPA / 256, HEADS, BATCH), 256>>>();
    out_gemm<<<dim3(SPA / BN, C_CH / BM, BATCH), 256>>>(w_out, b_out, y);
}

// round 5
// speedup vs baseline: 1.5335x; 1.0718x over previous
#include <cuda_runtime.h>
#include <math.h>

#define C_CH   128
#define SPA    4096
#define BATCH  2
#define HEADS  4
#define DHEAD  32
#define GROUPS 32
#define CPG    4
#define HTOT   128
#define QKV_R  384
#define EPSV   1e-5f

#define NC     8                 // split-K chunks over keys
#define CHUNK  (SPA / NC)        // 512 keys per chunk

typedef unsigned long long ull;

// Scratch (device globals: allocation-free per harness rules)
__device__ float g_qkv [BATCH * QKV_R * SPA];
__device__ float g_ao  [BATCH * HTOT * SPA];
__device__ float g_mean[BATCH * GROUPS];
__device__ float g_rstd[BATCH * GROUPS];
__device__ float g_pacc[BATCH * HEADS * NC * DHEAD * SPA];
__device__ float g_pm  [BATCH * HEADS * NC * SPA];
__device__ float g_pl  [BATCH * HEADS * NC * SPA];

// ---- Blackwell packed f32x2 helpers ---------------------------------------
__device__ __forceinline__ void ffma2(ull& d, ull a, ull b) {
    asm("fma.rn.f32x2 %0, %1, %2, %0;" : "+l"(d) : "l"(a), "l"(b));
}
__device__ __forceinline__ ull fadd2(ull a, ull b) {
    ull r; asm("add.rn.f32x2 %0, %1, %2;" : "=l"(r) : "l"(a), "l"(b)); return r;
}
__device__ __forceinline__ ull fmul2(ull a, ull b) {
    ull r; asm("mul.rn.f32x2 %0, %1, %2;" : "=l"(r) : "l"(a), "l"(b)); return r;
}
__device__ __forceinline__ ull pack2(float x, float y) {
    ull r; asm("mov.b64 %0, {%1, %2};" : "=l"(r) : "f"(x), "f"(y)); return r;
}
__device__ __forceinline__ float2 unpack2(ull v) {
    float lo, hi; asm("mov.b64 {%0, %1}, %2;" : "=f"(lo), "=f"(hi) : "l"(v));
    return make_float2(lo, hi);
}

// ---------------------------------------------------------------------------
// 1) GroupNorm statistics
// ---------------------------------------------------------------------------
__global__ __launch_bounds__(256) void gn_stats(const float* __restrict__ x) {
    int bg = blockIdx.x;
    const float* p = x + (size_t)bg * (CPG * SPA);
    float s1 = 0.f, s2 = 0.f;
    for (int i = threadIdx.x; i < CPG * SPA; i += 256) {
        float v = p[i];
        s1 += v; s2 += v * v;
    }
    __shared__ float r1[8], r2[8];
    #pragma unroll
    for (int o = 16; o; o >>= 1) {
        s1 += __shfl_down_sync(0xffffffffu, s1, o);
        s2 += __shfl_down_sync(0xffffffffu, s2, o);
    }
    int w = threadIdx.x >> 5, l = threadIdx.x & 31;
    if (l == 0) { r1[w] = s1; r2[w] = s2; }
    __syncthreads();
    if (w == 0) {
        s1 = (l < 8) ? r1[l] : 0.f;
        s2 = (l < 8) ? r2[l] : 0.f;
        #pragma unroll
        for (int o = 4; o; o >>= 1) {
            s1 += __shfl_down_sync(0xffffffffu, s1, o);
            s2 += __shfl_down_sync(0xffffffffu, s2, o);
        }
        if (l == 0) {
            const float invN = 1.0f / (CPG * SPA);
            float mean = s1 * invN;
            float var  = s2 * invN - mean * mean;
            g_mean[bg] = mean;
            g_rstd[bg] = rsqrtf(var + EPSV);
        }
    }
}

// ---------------------------------------------------------------------------
// 2) QKV GEMM with fused GroupNorm on the activation load
// ---------------------------------------------------------------------------
#define BM 64
#define BN 64
#define BK 32

__global__ __launch_bounds__(256) void qkv_gemm(const float* __restrict__ x,
                                                const float* __restrict__ w,
                                                const float* __restrict__ gamma,
                                                const float* __restrict__ beta) {
    int b  = blockIdx.z;
    int m0 = blockIdx.y * BM;
    int n0 = blockIdx.x * BN;
    __shared__ float As[BM * BK];
    __shared__ float Bs[BK * BN];
    int tid = threadIdx.x;
    int tx = tid & 15, ty = tid >> 4;
    float acc[4][4] = {};
    const float* xb = x + (size_t)b * C_CH * SPA;

    for (int k0 = 0; k0 < C_CH; k0 += BK) {
        for (int i = tid; i < BM * BK; i += 256) {
            int row = i / BK, col = i % BK;
            As[i] = w[(size_t)(m0 + row) * C_CH + k0 + col];
        }
        for (int i = tid; i < BK * BN; i += 256) {
            int kk = i / BN, j = i % BN;
            int c = k0 + kk;
            int g = c >> 2;
            float mv = g_mean[b * GROUPS + g];
            float rs = g_rstd[b * GROUPS + g];
            float v = xb[(size_t)c * SPA + n0 + j];
            Bs[i] = (v - mv) * rs * gamma[c] + beta[c];
        }
        __syncthreads();
        #pragma unroll
        for (int kk = 0; kk < BK; kk++) {
            float a[4], bb[4];
            #pragma unroll
            for (int i = 0; i < 4; i++) a[i] = As[(ty * 4 + i) * BK + kk];
            #pragma unroll
            for (int j = 0; j < 4; j++) bb[j] = Bs[kk * BN + tx * 4 + j];
            #pragma unroll
            for (int i = 0; i < 4; i++)
                #pragma unroll
                for (int j = 0; j < 4; j++) acc[i][j] += a[i] * bb[j];
        }
        __syncthreads();
    }
    float* outb = g_qkv + (size_t)b * QKV_R * SPA;
    #pragma unroll
    for (int i = 0; i < 4; i++)
        #pragma unroll
        for (int j = 0; j < 4; j++)
            outb[(size_t)(m0 + ty * 4 + i) * SPA + n0 + tx * 4 + j] = acc[i][j];
}

// ---------------------------------------------------------------------------
// 3a) Flash attention partial: 2 queries per thread (t and t+128 of a
//     256-query tile) sharing every K/V smem read. Packed f32x2 math.
//     Grid: (16, HEADS*NC=32, 2) = 1024 blocks of 128 threads.
// ---------------------------------------------------------------------------
#define TQ 256
#define TJ 64
#define KROW 36   // padded row: 9 float4 (144 B)

__global__ __launch_bounds__(128) void attn_partial() {
    int qt = blockIdx.x;
    int nc = blockIdx.y;                 // n*NC + chunk
    int b  = blockIdx.z;
    int n  = nc >> 3, c = nc & (NC - 1);
    int t  = threadIdx.x;

    __shared__ __align__(16) float smem_buf[2 * TJ * KROW];   // 18432 B
    float* sk = smem_buf;
    float* sv = smem_buf + TJ * KROW;

    const float* qkv_b = g_qkv + (size_t)b * QKV_R * SPA;
    const float* qptr = qkv_b + (size_t)(n * DHEAD) * SPA;
    const float* kptr = qkv_b + (size_t)(HTOT + n * DHEAD) * SPA;
    const float* vptr = qkv_b + (size_t)(2 * HTOT + n * DHEAD) * SPA;
    int s0 = qt * TQ;

    const float scale = 0.17677669529663687f;   // 1/sqrt(32)
    ull qA[16], qB[16];
    // stage queries s0+t (half 0) and s0+128+t (half 1) through smem
    #pragma unroll
    for (int h = 0; h < 2; h++) {
        __syncthreads();
        for (int i = t; i < 128 * DHEAD; i += 128) {
            int d = i >> 7, sl = i & 127;
            smem_buf[sl * 33 + d] = qptr[(size_t)d * SPA + s0 + h * 128 + sl];
        }
        __syncthreads();
        if (h == 0) {
            #pragma unroll
            for (int i = 0; i < 16; i++)
                qA[i] = pack2(smem_buf[t * 33 + 2 * i] * scale,
                              smem_buf[t * 33 + 2 * i + 1] * scale);
        } else {
            #pragma unroll
            for (int i = 0; i < 16; i++)
                qB[i] = pack2(smem_buf[t * 33 + 2 * i] * scale,
                              smem_buf[t * 33 + 2 * i + 1] * scale);
        }
    }
    __syncthreads();

    float mA = -1e30f, lA = 0.f, mB = -1e30f, lB = 0.f;
    ull accA[16], accB[16];
    #pragma unroll
    for (int i = 0; i < 16; i++) { accA[i] = 0ull; accB[i] = 0ull; }

    int jbeg = c * CHUNK, jend = jbeg + CHUNK;
    for (int j0 = jbeg; j0 < jend; j0 += TJ) {
        // fill K/V tile: coalesced LDG.32 x4, conflict-free STS.128
        for (int i = t; i < TJ * 8; i += 128) {
            int j = i & (TJ - 1), d4 = i >> 6;
            const float* kp = kptr + (size_t)(d4 * 4) * SPA + j0 + j;
            float4 kk;
            kk.x = kp[0]; kk.y = kp[SPA]; kk.z = kp[2 * SPA]; kk.w = kp[3 * SPA];
            *(float4*)&sk[j * KROW + d4 * 4] = kk;
            const float* vp = vptr + (size_t)(d4 * 4) * SPA + j0 + j;
            float4 vv;
            vv.x = vp[0]; vv.y = vp[SPA]; vv.z = vp[2 * SPA]; vv.w = vp[3 * SPA];
            *(float4*)&sv[j * KROW + d4 * 4] = vv;
        }
        __syncthreads();

        for (int j = 0; j < TJ; j++) {
            const ulonglong2* kr = (const ulonglong2*)&sk[j * KROW];
            ull a0 = 0, a1 = 0, a2 = 0, a3 = 0;      // q-A dot splits
            ull b0 = 0, b1 = 0, b2 = 0, b3 = 0;      // q-B dot splits
            #pragma unroll
            for (int g = 0; g < 8; g += 2) {
                ulonglong2 k0 = kr[g], k1 = kr[g + 1];
                ffma2(a0, qA[2 * g + 0], k0.x);
                ffma2(a1, qA[2 * g + 1], k0.y);
                ffma2(a2, qA[2 * g + 2], k1.x);
                ffma2(a3, qA[2 * g + 3], k1.y);
                ffma2(b0, qB[2 * g + 0], k0.x);
                ffma2(b1, qB[2 * g + 1], k0.y);
                ffma2(b2, qB[2 * g + 2], k1.x);
                ffma2(b3, qB[2 * g + 3], k1.y);
            }
            a0 = fadd2(fadd2(a0, a1), fadd2(a2, a3));
            b0 = fadd2(fadd2(b0, b1), fadd2(b2, b3));
            float2 da = unpack2(a0);
            float2 db = unpack2(b0);
            float scA = da.x + da.y;
            float scB = db.x + db.y;

            if (scA > mA) {                      // rare after warmup
                float corr = __expf(mA - scA);
                ull cc = pack2(corr, corr);
                lA *= corr;
                #pragma unroll
                for (int i = 0; i < 16; i++) accA[i] = fmul2(accA[i], cc);
                mA = scA;
            }
            if (scB > mB) {
                float corr = __expf(mB - scB);
                ull cc = pack2(corr, corr);
                lB *= corr;
                #pragma unroll
                for (int i = 0; i < 16; i++) accB[i] = fmul2(accB[i], cc);
                mB = scB;
            }
            float pA = __expf(scA - mA);
            float pB = __expf(scB - mB);
            lA += pA; lB += pB;
            ull ppA = pack2(pA, pA);
            ull ppB = pack2(pB, pB);
            const ulonglong2* vr = (const ulonglong2*)&sv[j * KROW];
            #pragma unroll
            for (int g = 0; g < 8; g++) {
                ulonglong2 vv = vr[g];
                ffma2(accA[2 * g + 0], ppA, vv.x);
                ffma2(accA[2 * g + 1], ppA, vv.y);
                ffma2(accB[2 * g + 0], ppB, vv.x);
                ffma2(accB[2 * g + 1], ppB, vv.y);
            }
        }
        __syncthreads();
    }

    // write partials (unnormalized); warp writes are coalesced (32 lanes
    // consecutive at s0+t, and at s0+128+t)
    size_t base = (size_t)(b * HEADS + n) * NC + c;
    g_pm[base * SPA + s0 + t]       = mA;
    g_pl[base * SPA + s0 + t]       = lA;
    g_pm[base * SPA + s0 + 128 + t] = mB;
    g_pl[base * SPA + s0 + 128 + t] = lB;
    float* pa = g_pacc + base * (DHEAD * SPA);
    #pragma unroll
    for (int i = 0; i < 16; i++) {
        float2 va = unpack2(accA[i]);
        float2 vb = unpack2(accB[i]);
        pa[(size_t)(2 * i + 0) * SPA + s0 + t]       = va.x;
        pa[(size_t)(2 * i + 1) * SPA + s0 + t]       = va.y;
        pa[(size_t)(2 * i + 0) * SPA + s0 + 128 + t] = vb.x;
        pa[(size_t)(2 * i + 1) * SPA + s0 + 128 + t] = vb.y;
    }
}

// ---------------------------------------------------------------------------
// 3b) Combine split-K partials -> g_ao. Parallelized over d (4 chunks of 8).
//     Grid: (SPA/256=16, HEADS*4=16, BATCH=2) = 512 blocks of 256 threads.
// ---------------------------------------------------------------------------
__global__ __launch_bounds__(256) void attn_combine() {
    int t = threadIdx.x;
    int s = blockIdx.x * 256 + t;
    int yb = blockIdx.y;
    int n = yb >> 2, dbase = (yb & 3) * 8;
    int b = blockIdx.z;
    size_t base = (size_t)(b * HEADS + n) * NC;

    float pm[NC];
    float m = -1e30f;
    #pragma unroll
    for (int c = 0; c < NC; c++) {
        pm[c] = g_pm[(base + c) * SPA + s];
        m = fmaxf(m, pm[c]);
    }
    float wgt[NC];
    float L = 0.f;
    #pragma unroll
    for (int c = 0; c < NC; c++) {
        wgt[c] = __expf(pm[c] - m);
        L += g_pl[(base + c) * SPA + s] * wgt[c];
    }
    float invL = 1.0f / L;
    #pragma unroll
    for (int c = 0; c < NC; c++) wgt[c] *= invL;

    float* ao = g_ao + ((size_t)b * HTOT + n * DHEAD) * SPA;
    #pragma unroll
    for (int dd = 0; dd < 8; dd++) {
        int d = dbase + dd;
        float a = 0.f;
        #pragma unroll
        for (int c = 0; c < NC; c++)
            a += g_pacc[((base + c) * DHEAD + d) * SPA + s] * wgt[c];
        ao[(size_t)d * SPA + s] = a;
    }
}

// ---------------------------------------------------------------------------
// 4) Output projection
// ---------------------------------------------------------------------------
__global__ __launch_bounds__(256) void out_gemm(const float* __restrict__ w,
                                                const float* __restrict__ bias,
                                                float* __restrict__ y) {
    int b  = blockIdx.z;
    int m0 = blockIdx.y * BM;
    int n0 = blockIdx.x * BN;
    __shared__ float As[BM * BK];
    __shared__ float Bs[BK * BN];
    int tid = threadIdx.x;
    int tx = tid & 15, ty = tid >> 4;
    float acc[4][4] = {};
    const float* ab = g_ao + (size_t)b * HTOT * SPA;

    for (int k0 = 0; k0 < HTOT; k0 += BK) {
        for (int i = tid; i < BM * BK; i += 256) {
            int row = i / BK, col = i % BK;
            As[i] = w[(size_t)(m0 + row) * HTOT + k0 + col];
        }
        for (int i = tid; i < BK * BN; i += 256) {
            int kk = i / BN, j = i % BN;
            Bs[i] = ab[(size_t)(k0 + kk) * SPA + n0 + j];
        }
        __syncthreads();
        #pragma unroll
        for (int kk = 0; kk < BK; kk++) {
            float a[4], bb[4];
            #pragma unroll
            for (int i = 0; i < 4; i++) a[i] = As[(ty * 4 + i) * BK + kk];
            #pragma unroll
            for (int j = 0; j < 4; j++) bb[j] = Bs[kk * BN + tx * 4 + j];
            #pragma unroll
            for (int i = 0; i < 4; i++)
                #pragma unroll
                for (int j = 0; j < 4; j++) acc[i][j] += a[i] * bb[j];
        }
        __syncthreads();
    }
    #pragma unroll
    for (int i = 0; i < 4; i++) {
        float bv = bias[m0 + ty * 4 + i];
        #pragma unroll
        for (int j = 0; j < 4; j++)
            y[(size_t)(b * C_CH + m0 + ty * 4 + i) * SPA + n0 + tx * 4 + j] =
                acc[i][j] + bv;
    }
}

// ---------------------------------------------------------------------------
extern "C" void kernel_launch(void* const* d_in, const int* in_sizes, int n_in,
                              void* d_out, int out_size) {
    const float* x     = (const float*)d_in[0];
    const float* gamma = (const float*)d_in[1];
    const float* beta  = (const float*)d_in[2];
    const float* w_qkv = (const float*)d_in[3];
    const float* w_out = (const float*)d_in[4];
    const float* b_out = (const float*)d_in[5];
    float* y = (float*)d_out;

    gn_stats<<<BATCH * GROUPS, 256>>>(x);
    qkv_gemm<<<dim3(SPA / BN, QKV_R / BM, BATCH), 256>>>(x, w_qkv, gamma, beta);
    attn_partial<<<dim3(SPA / TQ, HEADS * NC, BATCH), 128>>>();
    attn_combine<<<dim3(SPA / 256, HEADS * 4, BATCH), 256>>>();
    out_gemm<<<dim3(SPA / BN, C_CH / BM, BATCH), 256>>>(w_out, b_out, y);
}

// round 8
// speedup vs baseline: 1.8518x; 1.2076x over previous
#include <cuda_runtime.h>
#include <math.h>

#define C_CH   128
#define SPA    4096
#define BATCH  2
#define HEADS  4
#define DHEAD  32
#define GROUPS 32
#define CPG    4
#define HTOT   128
#define QKV_R  384
#define EPSV   1e-5f

#define NC     8                 // split-K chunks over keys
#define CHUNK  (SPA / NC)        // 512 keys per chunk

typedef unsigned long long ull;

// Scratch (device globals: allocation-free per harness rules)
__device__ float g_qkv [BATCH * QKV_R * SPA];
__device__ float g_ao  [BATCH * HTOT * SPA];
__device__ float g_mean[BATCH * GROUPS];
__device__ float g_rstd[BATCH * GROUPS];
__device__ float g_pacc[BATCH * HEADS * NC * DHEAD * SPA];
__device__ float g_pm  [BATCH * HEADS * NC * SPA];
__device__ float g_pl  [BATCH * HEADS * NC * SPA];

// ---- Blackwell packed f32x2 helpers ---------------------------------------
__device__ __forceinline__ void ffma2(ull& d, ull a, ull b) {
    asm("fma.rn.f32x2 %0, %1, %2, %0;" : "+l"(d) : "l"(a), "l"(b));
}
__device__ __forceinline__ ull fadd2(ull a, ull b) {
    ull r; asm("add.rn.f32x2 %0, %1, %2;" : "=l"(r) : "l"(a), "l"(b)); return r;
}
__device__ __forceinline__ ull fmul2(ull a, ull b) {
    ull r; asm("mul.rn.f32x2 %0, %1, %2;" : "=l"(r) : "l"(a), "l"(b)); return r;
}
__device__ __forceinline__ ull pack2(float x, float y) {
    ull r; asm("mov.b64 %0, {%1, %2};" : "=l"(r) : "f"(x), "f"(y)); return r;
}
__device__ __forceinline__ float2 unpack2(ull v) {
    float lo, hi; asm("mov.b64 {%0, %1}, %2;" : "=f"(lo), "=f"(hi) : "l"(v));
    return make_float2(lo, hi);
}
__device__ __forceinline__ float ex2(float x) {   // raw MUFU, log2-domain softmax
    float r; asm("ex2.approx.ftz.f32 %0, %1;" : "=f"(r) : "f"(x)); return r;
}

// ---------------------------------------------------------------------------
// 1) GroupNorm statistics
// ---------------------------------------------------------------------------
__global__ __launch_bounds__(256) void gn_stats(const float* __restrict__ x) {
    int bg = blockIdx.x;
    const float* p = x + (size_t)bg * (CPG * SPA);
    float s1 = 0.f, s2 = 0.f;
    for (int i = threadIdx.x; i < CPG * SPA; i += 256) {
        float v = p[i];
        s1 += v; s2 += v * v;
    }
    __shared__ float r1[8], r2[8];
    #pragma unroll
    for (int o = 16; o; o >>= 1) {
        s1 += __shfl_down_sync(0xffffffffu, s1, o);
        s2 += __shfl_down_sync(0xffffffffu, s2, o);
    }
    int w = threadIdx.x >> 5, l = threadIdx.x & 31;
    if (l == 0) { r1[w] = s1; r2[w] = s2; }
    __syncthreads();
    if (w == 0) {
        s1 = (l < 8) ? r1[l] : 0.f;
        s2 = (l < 8) ? r2[l] : 0.f;
        #pragma unroll
        for (int o = 4; o; o >>= 1) {
            s1 += __shfl_down_sync(0xffffffffu, s1, o);
            s2 += __shfl_down_sync(0xffffffffu, s2, o);
        }
        if (l == 0) {
            const float invN = 1.0f / (CPG * SPA);
            float mean = s1 * invN;
            float var  = s2 * invN - mean * mean;
            g_mean[bg] = mean;
            g_rstd[bg] = rsqrtf(var + EPSV);
        }
    }
}

// ---------------------------------------------------------------------------
// 2) QKV GEMM with fused GroupNorm on the activation load
// ---------------------------------------------------------------------------
#define BM 64
#define BN 64
#define BK 32

__global__ __launch_bounds__(256) void qkv_gemm(const float* __restrict__ x,
                                                const float* __restrict__ w,
                                                const float* __restrict__ gamma,
                                                const float* __restrict__ beta) {
    int b  = blockIdx.z;
    int m0 = blockIdx.y * BM;
    int n0 = blockIdx.x * BN;
    __shared__ float As[BM * BK];
    __shared__ float Bs[BK * BN];
    int tid = threadIdx.x;
    int tx = tid & 15, ty = tid >> 4;
    float acc[4][4] = {};
    const float* xb = x + (size_t)b * C_CH * SPA;

    for (int k0 = 0; k0 < C_CH; k0 += BK) {
        for (int i = tid; i < BM * BK; i += 256) {
            int row = i / BK, col = i % BK;
            As[i] = w[(size_t)(m0 + row) * C_CH + k0 + col];
        }
        for (int i = tid; i < BK * BN; i += 256) {
            int kk = i / BN, j = i % BN;
            int c = k0 + kk;
            int g = c >> 2;
            float mv = g_mean[b * GROUPS + g];
            float rs = g_rstd[b * GROUPS + g];
            float v = xb[(size_t)c * SPA + n0 + j];
            Bs[i] = (v - mv) * rs * gamma[c] + beta[c];
        }
        __syncthreads();
        #pragma unroll
        for (int kk = 0; kk < BK; kk++) {
            float a[4], bb[4];
            #pragma unroll
            for (int i = 0; i < 4; i++) a[i] = As[(ty * 4 + i) * BK + kk];
            #pragma unroll
            for (int j = 0; j < 4; j++) bb[j] = Bs[kk * BN + tx * 4 + j];
            #pragma unroll
            for (int i = 0; i < 4; i++)
                #pragma unroll
                for (int j = 0; j < 4; j++) acc[i][j] += a[i] * bb[j];
        }
        __syncthreads();
    }
    float* outb = g_qkv + (size_t)b * QKV_R * SPA;
    #pragma unroll
    for (int i = 0; i < 4; i++)
        #pragma unroll
        for (int j = 0; j < 4; j++)
            outb[(size_t)(m0 + ty * 4 + i) * SPA + n0 + tx * 4 + j] = acc[i][j];
}

// ---------------------------------------------------------------------------
// 3a) Flash attention partial: 2 queries/thread, keys processed in batches of
//     4 with phase separation (QK dots | batched max+exp | PV) for ILP.
//     Softmax in log2 domain (scale*log2e folded into q; raw ex2.approx).
//     Grid: (16, HEADS*NC=32, 2) = 1024 blocks of 128 threads.
// ---------------------------------------------------------------------------
#define TQ 256
#define TJ 64
#define KROW 36   // padded row: 9 float4 (144 B)

__global__ __launch_bounds__(128) void attn_partial() {
    int qt = blockIdx.x;
    int nc = blockIdx.y;                 // n*NC + chunk
    int b  = blockIdx.z;
    int n  = nc >> 3, c = nc & (NC - 1);
    int t  = threadIdx.x;

    __shared__ __align__(16) float smem_buf[2 * TJ * KROW];   // 18432 B
    float* sk = smem_buf;
    float* sv = smem_buf + TJ * KROW;

    const float* qkv_b = g_qkv + (size_t)b * QKV_R * SPA;
    const float* qptr = qkv_b + (size_t)(n * DHEAD) * SPA;
    const float* kptr = qkv_b + (size_t)(HTOT + n * DHEAD) * SPA;
    const float* vptr = qkv_b + (size_t)(2 * HTOT + n * DHEAD) * SPA;
    int s0 = qt * TQ;

    // scale * log2(e): softmax in log2 domain
    const float scale2 = 0.17677669529663687f * 1.4426950408889634f;
    ull qA[16], qB[16];
    #pragma unroll
    for (int h = 0; h < 2; h++) {
        __syncthreads();
        for (int i = t; i < 128 * DHEAD; i += 128) {
            int d = i >> 7, sl = i & 127;
            smem_buf[sl * 33 + d] = qptr[(size_t)d * SPA + s0 + h * 128 + sl];
        }
        __syncthreads();
        if (h == 0) {
            #pragma unroll
            for (int i = 0; i < 16; i++)
                qA[i] = pack2(smem_buf[t * 33 + 2 * i] * scale2,
                              smem_buf[t * 33 + 2 * i + 1] * scale2);
        } else {
            #pragma unroll
            for (int i = 0; i < 16; i++)
                qB[i] = pack2(smem_buf[t * 33 + 2 * i] * scale2,
                              smem_buf[t * 33 + 2 * i + 1] * scale2);
        }
    }
    __syncthreads();

    float mA = -1e30f, lA = 0.f, mB = -1e30f, lB = 0.f;
    ull accA[16], accB[16];
    #pragma unroll
    for (int i = 0; i < 16; i++) { accA[i] = 0ull; accB[i] = 0ull; }

    int jbeg = c * CHUNK, jend = jbeg + CHUNK;
    for (int j0 = jbeg; j0 < jend; j0 += TJ) {
        // fill K/V tile: coalesced LDG.32 x4, conflict-free STS.128
        for (int i = t; i < TJ * 8; i += 128) {
            int j = i & (TJ - 1), d4 = i >> 6;
            const float* kp = kptr + (size_t)(d4 * 4) * SPA + j0 + j;
            float4 kk;
            kk.x = kp[0]; kk.y = kp[SPA]; kk.z = kp[2 * SPA]; kk.w = kp[3 * SPA];
            *(float4*)&sk[j * KROW + d4 * 4] = kk;
            const float* vp = vptr + (size_t)(d4 * 4) * SPA + j0 + j;
            float4 vv;
            vv.x = vp[0]; vv.y = vp[SPA]; vv.z = vp[2 * SPA]; vv.w = vp[3 * SPA];
            *(float4*)&sv[j * KROW + d4 * 4] = vv;
        }
        __syncthreads();

        #pragma unroll 1
        for (int jb = 0; jb < TJ; jb += 4) {
            // ---- Phase 1: 8 independent score dots (4 keys x 2 queries) ----
            float scA4[4], scB4[4];
            #pragma unroll
            for (int jj = 0; jj < 4; jj++) {
                const ulonglong2* kr = (const ulonglong2*)&sk[(jb + jj) * KROW];
                ull a0 = 0, a1 = 0, b0 = 0, b1 = 0;
                #pragma unroll
                for (int g = 0; g < 8; g += 2) {
                    ulonglong2 k0 = kr[g], k1 = kr[g + 1];
                    ffma2(a0, qA[2 * g + 0], k0.x);
                    ffma2(a1, qA[2 * g + 1], k0.y);
                    ffma2(a0, qA[2 * g + 2], k1.x);
                    ffma2(a1, qA[2 * g + 3], k1.y);
                    ffma2(b0, qB[2 * g + 0], k0.x);
                    ffma2(b1, qB[2 * g + 1], k0.y);
                    ffma2(b0, qB[2 * g + 2], k1.x);
                    ffma2(b1, qB[2 * g + 3], k1.y);
                }
                a0 = fadd2(a0, a1);
                b0 = fadd2(b0, b1);
                float2 da = unpack2(a0), db = unpack2(b0);
                scA4[jj] = da.x + da.y;
                scB4[jj] = db.x + db.y;
            }

            // ---- Phase 2: batched max update + 8 pipelined ex2 ----
            float bmA = fmaxf(fmaxf(scA4[0], scA4[1]), fmaxf(scA4[2], scA4[3]));
            float bmB = fmaxf(fmaxf(scB4[0], scB4[1]), fmaxf(scB4[2], scB4[3]));
            if (bmA > mA) {                      // rare after warmup
                float corr = ex2(mA - bmA);
                ull cc = pack2(corr, corr);
                lA *= corr;
                #pragma unroll
                for (int i = 0; i < 16; i++) accA[i] = fmul2(accA[i], cc);
                mA = bmA;
            }
            if (bmB > mB) {
                float corr = ex2(mB - bmB);
                ull cc = pack2(corr, corr);
                lB *= corr;
                #pragma unroll
                for (int i = 0; i < 16; i++) accB[i] = fmul2(accB[i], cc);
                mB = bmB;
            }
            float pA4[4], pB4[4];
            #pragma unroll
            for (int jj = 0; jj < 4; jj++) {
                pA4[jj] = ex2(scA4[jj] - mA);
                pB4[jj] = ex2(scB4[jj] - mB);
            }
            lA += (pA4[0] + pA4[1]) + (pA4[2] + pA4[3]);
            lB += (pB4[0] + pB4[1]) + (pB4[2] + pB4[3]);

            // ---- Phase 3: PV accumulate (256 independent ffma2) ----
            #pragma unroll
            for (int jj = 0; jj < 4; jj++) {
                const ulonglong2* vr = (const ulonglong2*)&sv[(jb + jj) * KROW];
                ull ppA = pack2(pA4[jj], pA4[jj]);
                ull ppB = pack2(pB4[jj], pB4[jj]);
                #pragma unroll
                for (int g = 0; g < 8; g++) {
                    ulonglong2 vv = vr[g];
                    ffma2(accA[2 * g + 0], ppA, vv.x);
                    ffma2(accA[2 * g + 1], ppA, vv.y);
                    ffma2(accB[2 * g + 0], ppB, vv.x);
                    ffma2(accB[2 * g + 1], ppB, vv.y);
                }
            }
        }
        __syncthreads();
    }

    // write partials (unnormalized); m is in log2 domain — combine matches
    size_t base = (size_t)(b * HEADS + n) * NC + c;
    g_pm[base * SPA + s0 + t]       = mA;
    g_pl[base * SPA + s0 + t]       = lA;
    g_pm[base * SPA + s0 + 128 + t] = mB;
    g_pl[base * SPA + s0 + 128 + t] = lB;
    float* pa = g_pacc + base * (DHEAD * SPA);
    #pragma unroll
    for (int i = 0; i < 16; i++) {
        float2 va = unpack2(accA[i]);
        float2 vb = unpack2(accB[i]);
        pa[(size_t)(2 * i + 0) * SPA + s0 + t]       = va.x;
        pa[(size_t)(2 * i + 1) * SPA + s0 + t]       = va.y;
        pa[(size_t)(2 * i + 0) * SPA + s0 + 128 + t] = vb.x;
        pa[(size_t)(2 * i + 1) * SPA + s0 + 128 + t] = vb.y;
    }
}

// ---------------------------------------------------------------------------
// 3b) Combine split-K partials -> g_ao (m/l are log2-domain: weights use ex2)
// ---------------------------------------------------------------------------
__global__ __launch_bounds__(256) void attn_combine() {
    int t = threadIdx.x;
    int s = blockIdx.x * 256 + t;
    int yb = blockIdx.y;
    int n = yb >> 2, dbase = (yb & 3) * 8;
    int b = blockIdx.z;
    size_t base = (size_t)(b * HEADS + n) * NC;

    float pm[NC];
    float m = -1e30f;
    #pragma unroll
    for (int c = 0; c < NC; c++) {
        pm[c] = g_pm[(base + c) * SPA + s];
        m = fmaxf(m, pm[c]);
    }
    float wgt[NC];
    float L = 0.f;
    #pragma unroll
    for (int c = 0; c < NC; c++) {
        wgt[c] = ex2(pm[c] - m);
        L += g_pl[(base + c) * SPA + s] * wgt[c];
    }
    float invL = 1.0f / L;
    #pragma unroll
    for (int c = 0; c < NC; c++) wgt[c] *= invL;

    float* ao = g_ao + ((size_t)b * HTOT + n * DHEAD) * SPA;
    #pragma unroll
    for (int dd = 0; dd < 8; dd++) {
        int d = dbase + dd;
        float a = 0.f;
        #pragma unroll
        for (int c = 0; c < NC; c++)
            a += g_pacc[((base + c) * DHEAD + d) * SPA + s] * wgt[c];
        ao[(size_t)d * SPA + s] = a;
    }
}

// ---------------------------------------------------------------------------
// 4) Output projection
// ---------------------------------------------------------------------------
__global__ __launch_bounds__(256) void out_gemm(const float* __restrict__ w,
                                                const float* __restrict__ bias,
                                                float* __restrict__ y) {
    int b  = blockIdx.z;
    int m0 = blockIdx.y * BM;
    int n0 = blockIdx.x * BN;
    __shared__ float As[BM * BK];
    __shared__ float Bs[BK * BN];
    int tid = threadIdx.x;
    int tx = tid & 15, ty = tid >> 4;
    float acc[4][4] = {};
    const float* ab = g_ao + (size_t)b * HTOT * SPA;

    for (int k0 = 0; k0 < HTOT; k0 += BK) {
        for (int i = tid; i < BM * BK; i += 256) {
            int row = i / BK, col = i % BK;
            As[i] = w[(size_t)(m0 + row) * HTOT + k0 + col];
        }
        for (int i = tid; i < BK * BN; i += 256) {
            int kk = i / BN, j = i % BN;
            Bs[i] = ab[(size_t)(k0 + kk) * SPA + n0 + j];
        }
        __syncthreads();
        #pragma unroll
        for (int kk = 0; kk < BK; kk++) {
            float a[4], bb[4];
            #pragma unroll
            for (int i = 0; i < 4; i++) a[i] = As[(ty * 4 + i) * BK + kk];
            #pragma unroll
            for (int j = 0; j < 4; j++) bb[j] = Bs[kk * BN + tx * 4 + j];
            #pragma unroll
            for (int i = 0; i < 4; i++)
                #pragma unroll
                for (int j = 0; j < 4; j++) acc[i][j] += a[i] * bb[j];
        }
        __syncthreads();
    }
    #pragma unroll
    for (int i = 0; i < 4; i++) {
        float bv = bias[m0 + ty * 4 + i];
        #pragma unroll
        for (int j = 0; j < 4; j++)
            y[(size_t)(b * C_CH + m0 + ty * 4 + i) * SPA + n0 + tx * 4 + j] =
                acc[i][j] + bv;
    }
}

// ---------------------------------------------------------------------------
extern "C" void kernel_launch(void* const* d_in, const int* in_sizes, int n_in,
                              void* d_out, int out_size) {
    const float* x     = (const float*)d_in[0];
    const float* gamma = (const float*)d_in[1];
    const float* beta  = (const float*)d_in[2];
    const float* w_qkv = (const float*)d_in[3];
    const float* w_out = (const float*)d_in[4];
    const float* b_out = (const float*)d_in[5];
    float* y = (float*)d_out;

    gn_stats<<<BATCH * GROUPS, 256>>>(x);
    qkv_gemm<<<dim3(SPA / BN, QKV_R / BM, BATCH), 256>>>(x, w_qkv, gamma, beta);
    attn_partial<<<dim3(SPA / TQ, HEADS * NC, BATCH), 128>>>();
    attn_combine<<<dim3(SPA / 256, HEADS * 4, BATCH), 256>>>();
    out_gemm<<<dim3(SPA / BN, C_CH / BM, BATCH), 256>>>(w_out, b_out, y);
}